// round 1
// baseline (speedup 1.0000x reference)
#include <cuda_runtime.h>

#define BATCH 16
#define NPTS  896      // 512 real + 384 pad
#define NREAL 512
#define DIM   256
#define NPAD  384

// ---------------- scratch (static device globals; no runtime alloc) ----------
__device__ float d_f1n[BATCH*NPTS*DIM];          // normalized concat(x1,x3)
__device__ float d_f2n[BATCH*NPTS*DIM];          // normalized concat(x2,x4)
__device__ float d_C  [BATCH*NREAL*NREAL];       // sim block, then C in-place
__device__ float d_Ct [BATCH*NREAL*NREAL];       // C transpose
__device__ float d_rsum[BATCH*NPTS];             // sim.sum over j (rows)
__device__ float d_csum[BATCH*NPTS];             // sim.sum over i (cols)
__device__ float d_fA[BATCH*NREAL], d_gA[BATCH*NREAL];
__device__ float d_fB[BATCH*NREAL], d_gB[BATCH*NREAL];
__device__ float d_hinge;

// ---------------- zero accumulators ----------------
__global__ void zero_kernel() {
    int i = blockIdx.x * blockDim.x + threadIdx.x;
    if (i < BATCH*NPTS) { d_rsum[i] = 0.f; d_csum[i] = 0.f; }
    if (i == 0) d_hinge = 0.f;
}

// ---------------- row-normalize f1, f2 (warp per row) ----------------
__global__ __launch_bounds__(256) void norm_kernel(
    const float* __restrict__ x1, const float* __restrict__ x2,
    const float* __restrict__ x3, const float* __restrict__ x4)
{
    int w    = (blockIdx.x * 256 + threadIdx.x) >> 5;   // 0..28671
    int lane = threadIdx.x & 31;
    int tensor = w / (BATCH*NPTS);
    int r      = w - tensor * (BATCH*NPTS);
    int b = r / NPTS;
    int i = r - b * NPTS;

    const float* src;
    if (tensor == 0)
        src = (i < NREAL) ? x1 + ((size_t)b*NREAL + i)*DIM
                          : x3 + ((size_t)b*NPAD + (i-NREAL))*DIM;
    else
        src = (i < NREAL) ? x2 + ((size_t)b*NREAL + i)*DIM
                          : x4 + ((size_t)b*NPAD + (i-NREAL))*DIM;
    float* dst = (tensor ? d_f2n : d_f1n) + ((size_t)b*NPTS + i)*DIM;

    float4 v0 = *(const float4*)(src + lane*4);
    float4 v1 = *(const float4*)(src + 128 + lane*4);
    float ss = v0.x*v0.x + v0.y*v0.y + v0.z*v0.z + v0.w*v0.w
             + v1.x*v1.x + v1.y*v1.y + v1.z*v1.z + v1.w*v1.w;
    #pragma unroll
    for (int o = 16; o; o >>= 1) ss += __shfl_xor_sync(0xffffffffu, ss, o);
    float inv = 1.0f / fmaxf(sqrtf(ss), 1e-12f);

    float4 o0 = make_float4(v0.x*inv, v0.y*inv, v0.z*inv, v0.w*inv);
    float4 o1 = make_float4(v1.x*inv, v1.y*inv, v1.z*inv, v1.w*inv);
    *(float4*)(dst + lane*4)       = o0;
    *(float4*)(dst + 128 + lane*4) = o1;
}

// ---------------- sim = exp(10 * f1n @ f2nT); row/col sums; store 512x512 block
__global__ __launch_bounds__(256) void sim_kernel() {
    const int b  = blockIdx.z;
    const int ti = blockIdx.y * 64, tj = blockIdx.x * 64;
    const float* A = d_f1n + (size_t)b*NPTS*DIM;
    const float* B = d_f2n + (size_t)b*NPTS*DIM;
    __shared__ float As[16][68];
    __shared__ float Bs[16][68];
    __shared__ float rred[64], cred[64];

    const int tid  = threadIdx.y*16 + threadIdx.x;
    const int lrow = tid >> 2;
    const int lc4  = (tid & 3) * 4;

    float acc[4][4];
    #pragma unroll
    for (int r = 0; r < 4; r++)
        #pragma unroll
        for (int c = 0; c < 4; c++) acc[r][c] = 0.f;

    for (int k0 = 0; k0 < DIM; k0 += 16) {
        float4 av = *(const float4*)(A + (size_t)(ti+lrow)*DIM + k0 + lc4);
        float4 bv = *(const float4*)(B + (size_t)(tj+lrow)*DIM + k0 + lc4);
        As[lc4+0][lrow] = av.x; As[lc4+1][lrow] = av.y;
        As[lc4+2][lrow] = av.z; As[lc4+3][lrow] = av.w;
        Bs[lc4+0][lrow] = bv.x; Bs[lc4+1][lrow] = bv.y;
        Bs[lc4+2][lrow] = bv.z; Bs[lc4+3][lrow] = bv.w;
        __syncthreads();
        #pragma unroll
        for (int kk = 0; kk < 16; kk++) {
            float4 a4 = *(const float4*)&As[kk][threadIdx.y*4];
            float4 b4 = *(const float4*)&Bs[kk][threadIdx.x*4];
            float aa[4] = {a4.x, a4.y, a4.z, a4.w};
            float bb[4] = {b4.x, b4.y, b4.z, b4.w};
            #pragma unroll
            for (int r = 0; r < 4; r++)
                #pragma unroll
                for (int c = 0; c < 4; c++) acc[r][c] += aa[r]*bb[c];
        }
        __syncthreads();
    }

    if (tid < 64) { rred[tid] = 0.f; cred[tid] = 0.f; }
    __syncthreads();

    float rloc[4] = {0,0,0,0}, cloc[4] = {0,0,0,0};
    #pragma unroll
    for (int r = 0; r < 4; r++)
        #pragma unroll
        for (int c = 0; c < 4; c++) {
            float s = exp2f(acc[r][c] * 14.4269504088896341f);  // exp(10*g)
            acc[r][c] = s; rloc[r] += s; cloc[c] += s;
        }
    #pragma unroll
    for (int r = 0; r < 4; r++) atomicAdd(&rred[threadIdx.y*4 + r], rloc[r]);
    #pragma unroll
    for (int c = 0; c < 4; c++) atomicAdd(&cred[threadIdx.x*4 + c], cloc[c]);

    if (ti < NREAL && tj < NREAL) {
        #pragma unroll
        for (int r = 0; r < 4; r++) {
            int i = ti + threadIdx.y*4 + r;
            float4 v = make_float4(acc[r][0], acc[r][1], acc[r][2], acc[r][3]);
            *(float4*)(d_C + ((size_t)b*NREAL + i)*NREAL + tj + threadIdx.x*4) = v;
        }
    }
    __syncthreads();
    if (tid < 64) {
        atomicAdd(&d_rsum[b*NPTS + ti + tid], rred[tid]);
        atomicAdd(&d_csum[b*NPTS + tj + tid], cred[tid]);
    }
}

// ---------------- C = 1 - s/(c_j + r_i - s) in-place on 512 block; write Ct ----
__global__ void cmat_kernel() {   // block (32,8), grid (16,16,16)
    __shared__ float tile[32][33];
    int b = blockIdx.z, i0 = blockIdx.y*32, j0 = blockIdx.x*32;
    #pragma unroll
    for (int u = 0; u < 4; u++) {
        int i = i0 + threadIdx.y + u*8;
        int j = j0 + threadIdx.x;
        size_t idx = ((size_t)b*NREAL + i)*NREAL + j;
        float s  = d_C[idx];
        float cv = 1.0f - s / (d_csum[b*NPTS + j] + d_rsum[b*NPTS + i] - s);
        d_C[idx] = cv;
        tile[threadIdx.y + u*8][threadIdx.x] = cv;
    }
    __syncthreads();
    #pragma unroll
    for (int u = 0; u < 4; u++) {
        int jj = j0 + threadIdx.y + u*8;
        int ii = i0 + threadIdx.x;
        d_Ct[((size_t)b*NREAL + jj)*NREAL + ii] = tile[threadIdx.x][threadIdx.y + u*8];
    }
}

// ---------------- softmin: one warp per (dir, b, i) row ----------------
// mode 0: h=0, write raw (init).  mode 1: write 0.5*(prev+new).  mode 2: raw (final)
__global__ __launch_bounds__(256) void softmin_kernel(int mode, float eps, int par) {
    int gw   = (blockIdx.x*256 + threadIdx.x) >> 5;   // 0..16383
    int lane = threadIdx.x & 31;
    int dir  = gw >> 13;
    int rem  = gw & 8191;
    int b    = rem >> 9;
    int i    = rem & 511;

    const float* fin  = par ? d_fB : d_fA;
    const float* gin  = par ? d_gB : d_gA;
    float*       fout = par ? d_fA : d_fB;
    float*       gout = par ? d_gA : d_gB;

    const float* Crow = (dir ? d_Ct : d_C) + ((size_t)b*NREAL + i)*NREAL;
    const float* h    = (dir ? fin : gin) + b*NREAL;

    float t[16];
    float m = -3.0e38f;
    #pragma unroll
    for (int k = 0; k < 16; k++) {
        int j = (k << 5) + lane;
        float hv = (mode == 0) ? 0.0f : __ldg(&h[j]);
        t[k] = hv - __ldg(&Crow[j]);
        m = fmaxf(m, t[k]);
    }
    #pragma unroll
    for (int o = 16; o; o >>= 1) m = fmaxf(m, __shfl_xor_sync(0xffffffffu, m, o));

    float a = 1.44269504088896341f / eps;
    float s = 0.f;
    #pragma unroll
    for (int k = 0; k < 16; k++) s += exp2f((t[k] - m) * a);
    #pragma unroll
    for (int o = 16; o; o >>= 1) s += __shfl_xor_sync(0xffffffffu, s, o);

    if (lane == 0) {
        float out = -m - eps * 0.6931471805599453f * log2f(s);
        int idx = b*NREAL + i;
        if (dir == 0) fout[idx] = (mode == 1) ? 0.5f*(fin[idx] + out) : out;
        else          gout[idx] = (mode == 1) ? 0.5f*(gin[idx] + out) : out;
    }
}

// ---------------- hinge: sum relu(0.1 - x3 @ x4T) ----------------
__global__ __launch_bounds__(256) void hinge_kernel(
    const float* __restrict__ x3, const float* __restrict__ x4)
{
    const int b  = blockIdx.z;
    const int ti = blockIdx.y*64, tj = blockIdx.x*64;
    const float* A = x3 + (size_t)b*NPAD*DIM;
    const float* B = x4 + (size_t)b*NPAD*DIM;
    __shared__ float As[16][68];
    __shared__ float Bs[16][68];
    const int tid  = threadIdx.y*16 + threadIdx.x;
    const int lrow = tid >> 2;
    const int lc4  = (tid & 3) * 4;

    float acc[4][4];
    #pragma unroll
    for (int r = 0; r < 4; r++)
        #pragma unroll
        for (int c = 0; c < 4; c++) acc[r][c] = 0.f;

    for (int k0 = 0; k0 < DIM; k0 += 16) {
        float4 av = *(const float4*)(A + (size_t)(ti+lrow)*DIM + k0 + lc4);
        float4 bv = *(const float4*)(B + (size_t)(tj+lrow)*DIM + k0 + lc4);
        As[lc4+0][lrow] = av.x; As[lc4+1][lrow] = av.y;
        As[lc4+2][lrow] = av.z; As[lc4+3][lrow] = av.w;
        Bs[lc4+0][lrow] = bv.x; Bs[lc4+1][lrow] = bv.y;
        Bs[lc4+2][lrow] = bv.z; Bs[lc4+3][lrow] = bv.w;
        __syncthreads();
        #pragma unroll
        for (int kk = 0; kk < 16; kk++) {
            float4 a4 = *(const float4*)&As[kk][threadIdx.y*4];
            float4 b4 = *(const float4*)&Bs[kk][threadIdx.x*4];
            float aa[4] = {a4.x, a4.y, a4.z, a4.w};
            float bb[4] = {b4.x, b4.y, b4.z, b4.w};
            #pragma unroll
            for (int r = 0; r < 4; r++)
                #pragma unroll
                for (int c = 0; c < 4; c++) acc[r][c] += aa[r]*bb[c];
        }
        __syncthreads();
    }

    float hsum = 0.f;
    #pragma unroll
    for (int r = 0; r < 4; r++)
        #pragma unroll
        for (int c = 0; c < 4; c++) hsum += fmaxf(0.1f - acc[r][c], 0.f);

    #pragma unroll
    for (int o = 16; o; o >>= 1) hsum += __shfl_xor_sync(0xffffffffu, hsum, o);
    __shared__ float wsum[8];
    int warp = tid >> 5, lane = tid & 31;
    if (lane == 0) wsum[warp] = hsum;
    __syncthreads();
    if (tid == 0) {
        float t = 0.f;
        #pragma unroll
        for (int k = 0; k < 8; k++) t += wsum[k];
        atomicAdd(&d_hinge, t);
    }
}

// ---------------- final reduction: scon = mean_b(sum f + sum g) ----------------
__global__ void reduce_kernel(float* __restrict__ out) {
    float s = 0.f;
    for (int idx = threadIdx.x; idx < BATCH*NREAL; idx += 256)
        s += d_fB[idx] + d_gB[idx];
    #pragma unroll
    for (int o = 16; o; o >>= 1) s += __shfl_xor_sync(0xffffffffu, s, o);
    __shared__ float w[8];
    int warp = threadIdx.x >> 5, lane = threadIdx.x & 31;
    if (lane == 0) w[warp] = s;
    __syncthreads();
    if (threadIdx.x == 0) {
        float t = 0.f;
        #pragma unroll
        for (int k = 0; k < 8; k++) t += w[k];
        out[0] = d_hinge;
        out[1] = t * (1.0f / BATCH);
    }
}

// ---------------- launch ----------------
extern "C" void kernel_launch(void* const* d_in, const int* in_sizes, int n_in,
                              void* d_out, int out_size) {
    const float* x1 = (const float*)d_in[0];
    const float* x2 = (const float*)d_in[1];
    const float* x3 = (const float*)d_in[2];
    const float* x4 = (const float*)d_in[3];
    float* out = (float*)d_out;

    // geomloss epsilon schedule: [9, 9, 2.25, 0.5625, ..., 0.0025]
    static const float EPS[8] = {9.0f, 9.0f, 2.25f, 0.5625f, 0.140625f,
                                 0.03515625f, 0.0087890625f, 0.0025f};

    zero_kernel<<<56, 256>>>();
    norm_kernel<<<3584, 256>>>(x1, x2, x3, x4);
    sim_kernel<<<dim3(14,14,16), dim3(16,16)>>>();
    cmat_kernel<<<dim3(16,16,16), dim3(32,8)>>>();

    // init: f_ba, g_ab at eps=9, write into A buffers (par=1 -> out=A)
    softmin_kernel<<<2048, 256>>>(0, 9.0f, 1);
    // 8 symmetric averaged iterations (ping-pong A<->B; ends in A)
    for (int it = 0; it < 8; it++)
        softmin_kernel<<<2048, 256>>>(1, EPS[it], it & 1);
    // final extrapolation at eps=0.0025: read A, write B
    softmin_kernel<<<2048, 256>>>(2, 0.0025f, 0);

    hinge_kernel<<<dim3(6,6,16), dim3(16,16)>>>(x3, x4);
    reduce_kernel<<<1, 256>>>(out);
}

// round 3
// speedup vs baseline: 1.3803x; 1.3803x over previous
#include <cuda_runtime.h>
#include <cuda_bf16.h>

#define BATCH 16
#define NPTS  896
#define NREAL 512
#define DIM   256
#define NPAD  384

// ---------------- scratch ----------------
__device__ __nv_bfloat16 d_f1hi[BATCH*NPTS*DIM], d_f1lo[BATCH*NPTS*DIM];
__device__ __nv_bfloat16 d_f2hi[BATCH*NPTS*DIM], d_f2lo[BATCH*NPTS*DIM];
__device__ __nv_bfloat16 d_h3hi[BATCH*NPAD*DIM], d_h3lo[BATCH*NPAD*DIM];
__device__ __nv_bfloat16 d_h4hi[BATCH*NPAD*DIM], d_h4lo[BATCH*NPAD*DIM];
__device__ float d_C  [BATCH*NREAL*NREAL];
__device__ float d_Ct [BATCH*NREAL*NREAL];
__device__ float d_rsum[BATCH*NPTS];
__device__ float d_csum[BATCH*NPTS];
__device__ float d_fA[BATCH*NREAL], d_gA[BATCH*NREAL];
__device__ float d_fB[BATCH*NREAL], d_gB[BATCH*NREAL];
__device__ float d_hinge;

__device__ __forceinline__ void ldm4(unsigned r[4], unsigned addr) {
    asm volatile("ldmatrix.sync.aligned.m8n8.x4.shared.b16 {%0,%1,%2,%3}, [%4];\n"
        : "=r"(r[0]), "=r"(r[1]), "=r"(r[2]), "=r"(r[3]) : "r"(addr));
}

__device__ __forceinline__ void mma16816(float acc[4], const unsigned a[4],
                                         unsigned b0, unsigned b1) {
    asm volatile("mma.sync.aligned.m16n8k16.row.col.f32.bf16.bf16.f32 "
        "{%0,%1,%2,%3},{%4,%5,%6,%7},{%8,%9},{%0,%1,%2,%3};\n"
        : "+f"(acc[0]), "+f"(acc[1]), "+f"(acc[2]), "+f"(acc[3])
        : "r"(a[0]), "r"(a[1]), "r"(a[2]), "r"(a[3]), "r"(b0), "r"(b1));
}

// ---------------- zero ----------------
__global__ void zero_kernel() {
    int i = blockIdx.x * blockDim.x + threadIdx.x;
    if (i < BATCH*NPTS) { d_rsum[i] = 0.f; d_csum[i] = 0.f; }
    if (i == 0) d_hinge = 0.f;
}

// ---------------- prep: normalize + bf16 hi/lo split ----------------
__device__ __forceinline__ void split_store4(__nv_bfloat16* hi, __nv_bfloat16* lo,
                                             float4 v, float scale) {
    float a[4] = {v.x*scale, v.y*scale, v.z*scale, v.w*scale};
    __nv_bfloat16 h[4], l[4];
    #pragma unroll
    for (int i = 0; i < 4; i++) {
        h[i] = __float2bfloat16(a[i]);
        l[i] = __float2bfloat16(a[i] - __bfloat162float(h[i]));
    }
    *(uint2*)hi = *(uint2*)h;
    *(uint2*)lo = *(uint2*)l;
}

__global__ __launch_bounds__(256) void prep_kernel(
    const float* __restrict__ x1, const float* __restrict__ x2,
    const float* __restrict__ x3, const float* __restrict__ x4)
{
    int w    = (blockIdx.x * 256 + threadIdx.x) >> 5;
    int lane = threadIdx.x & 31;

    if (w < 2*BATCH*NPTS) {
        int tensor = w / (BATCH*NPTS);
        int r      = w - tensor * (BATCH*NPTS);
        int b = r / NPTS;
        int i = r - b * NPTS;
        const float* src;
        if (tensor == 0)
            src = (i < NREAL) ? x1 + ((size_t)b*NREAL + i)*DIM
                              : x3 + ((size_t)b*NPAD + (i-NREAL))*DIM;
        else
            src = (i < NREAL) ? x2 + ((size_t)b*NREAL + i)*DIM
                              : x4 + ((size_t)b*NPAD + (i-NREAL))*DIM;
        size_t off = ((size_t)b*NPTS + i)*DIM;
        __nv_bfloat16* hi = (tensor ? d_f2hi : d_f1hi) + off;
        __nv_bfloat16* lo = (tensor ? d_f2lo : d_f1lo) + off;

        float4 v0 = *(const float4*)(src + lane*4);
        float4 v1 = *(const float4*)(src + 128 + lane*4);
        float ss = v0.x*v0.x + v0.y*v0.y + v0.z*v0.z + v0.w*v0.w
                 + v1.x*v1.x + v1.y*v1.y + v1.z*v1.z + v1.w*v1.w;
        #pragma unroll
        for (int o = 16; o; o >>= 1) ss += __shfl_xor_sync(0xffffffffu, ss, o);
        float inv = 1.0f / fmaxf(sqrtf(ss), 1e-12f);
        split_store4(hi + lane*4,       lo + lane*4,       v0, inv);
        split_store4(hi + 128 + lane*4, lo + 128 + lane*4, v1, inv);
    } else {
        int w2 = w - 2*BATCH*NPTS;
        int tensor = w2 / (BATCH*NPAD);
        int r      = w2 - tensor * (BATCH*NPAD);
        int b = r / NPAD;
        int i = r - b * NPAD;
        const float* src = (tensor ? x4 : x3) + ((size_t)b*NPAD + i)*DIM;
        size_t off = ((size_t)b*NPAD + i)*DIM;
        __nv_bfloat16* hi = (tensor ? d_h4hi : d_h3hi) + off;
        __nv_bfloat16* lo = (tensor ? d_h4lo : d_h3lo) + off;
        float4 v0 = *(const float4*)(src + lane*4);
        float4 v1 = *(const float4*)(src + 128 + lane*4);
        split_store4(hi + lane*4,       lo + lane*4,       v0, 1.0f);
        split_store4(hi + 128 + lane*4, lo + 128 + lane*4, v1, 1.0f);
    }
}

// ---------------- shared 64x64 bf16-split MMA mainloop ----------------
__device__ __forceinline__ void mma_mainloop(
    const __nv_bfloat16* __restrict__ Ahi, const __nv_bfloat16* __restrict__ Alo,
    const __nv_bfloat16* __restrict__ Bhi, const __nv_bfloat16* __restrict__ Blo,
    int arow0, int brow0,
    __nv_bfloat16* sAhi, __nv_bfloat16* sAlo,
    __nv_bfloat16* sBhi, __nv_bfloat16* sBlo,
    float acc[4][4])
{
    const int tid = threadIdx.x;
    const int w = tid >> 5, l = tid & 31;
    const int wm = w & 3, wn = w >> 2;      // warp: m offset wm*16, n offset wn*32
    const int row = tid >> 2, g = tid & 3;  // load mapping: 64 rows x 4 chunks

    const int sArow = (wm*16 + (l & 15))*40 + ((l >> 4) * 8);
    unsigned aAhi = (unsigned)__cvta_generic_to_shared(&sAhi[sArow]);
    unsigned aAlo = (unsigned)__cvta_generic_to_shared(&sAlo[sArow]);
    const int sBrow = (wn*32 + (l & 7) + ((l >> 4) & 1)*8)*40 + (((l >> 3) & 1) * 8);
    unsigned aBhi0 = (unsigned)__cvta_generic_to_shared(&sBhi[sBrow]);
    unsigned aBlo0 = (unsigned)__cvta_generic_to_shared(&sBlo[sBrow]);
    const unsigned b16off = 16*40*2;   // +16 n-rows, in bytes

    for (int kc = 0; kc < DIM; kc += 32) {
        const size_t ga = ((size_t)(arow0 + row))*DIM + kc + g*8;
        const size_t gb = ((size_t)(brow0 + row))*DIM + kc + g*8;
        *(uint4*)&sAhi[row*40 + g*8] = *(const uint4*)&Ahi[ga];
        *(uint4*)&sAlo[row*40 + g*8] = *(const uint4*)&Alo[ga];
        *(uint4*)&sBhi[row*40 + g*8] = *(const uint4*)&Bhi[gb];
        *(uint4*)&sBlo[row*40 + g*8] = *(const uint4*)&Blo[gb];
        __syncthreads();
        #pragma unroll
        for (int ks = 0; ks < 32; ks += 16) {
            unsigned ahi[4], alo[4];
            unsigned bhi0[4], bhi1[4], blo0[4], blo1[4];
            ldm4(ahi, aAhi + ks*2);
            ldm4(alo, aAlo + ks*2);
            ldm4(bhi0, aBhi0 + ks*2);
            ldm4(bhi1, aBhi0 + b16off + ks*2);
            ldm4(blo0, aBlo0 + ks*2);
            ldm4(blo1, aBlo0 + b16off + ks*2);
            #pragma unroll
            for (int nt = 0; nt < 4; nt++) {
                const unsigned* bh = (nt < 2) ? bhi0 : bhi1;
                const unsigned* bl = (nt < 2) ? blo0 : blo1;
                unsigned bh0 = bh[(nt & 1)*2], bh1 = bh[(nt & 1)*2 + 1];
                unsigned bl0 = bl[(nt & 1)*2], bl1 = bl[(nt & 1)*2 + 1];
                mma16816(acc[nt], ahi, bh0, bh1);
                mma16816(acc[nt], ahi, bl0, bl1);
                mma16816(acc[nt], alo, bh0, bh1);
            }
        }
        __syncthreads();
    }
}

// ---------------- sim GEMM + exp + row/col sums + store 512-block ----------------
__global__ __launch_bounds__(256) void sim_mma_kernel() {
    __shared__ __nv_bfloat16 sAhi[64*40], sAlo[64*40], sBhi[64*40], sBlo[64*40];
    __shared__ float rred[64], cred[64];
    const int b = blockIdx.z;
    const int ti = blockIdx.y*64, tj = blockIdx.x*64;
    const size_t boff = (size_t)b*NPTS*DIM;

    float acc[4][4];
    #pragma unroll
    for (int nt = 0; nt < 4; nt++)
        #pragma unroll
        for (int k = 0; k < 4; k++) acc[nt][k] = 0.f;

    mma_mainloop(d_f1hi + boff, d_f1lo + boff, d_f2hi + boff, d_f2lo + boff,
                 ti, tj, sAhi, sAlo, sBhi, sBlo, acc);

    const int tid = threadIdx.x;
    const int w = tid >> 5, l = tid & 31;
    const int wm = w & 3, wn = w >> 2;
    const int gid = l >> 2, qid = l & 3;

    if (tid < 64) { rred[tid] = 0.f; cred[tid] = 0.f; }
    __syncthreads();

    const bool inC = (ti < NREAL) && (tj < NREAL);
    float rs0 = 0.f, rs1 = 0.f;
    #pragma unroll
    for (int nt = 0; nt < 4; nt++) {
        float e0 = exp2f(acc[nt][0] * 14.4269504088896341f);
        float e1 = exp2f(acc[nt][1] * 14.4269504088896341f);
        float e2 = exp2f(acc[nt][2] * 14.4269504088896341f);
        float e3 = exp2f(acc[nt][3] * 14.4269504088896341f);
        rs0 += e0 + e1;  rs1 += e2 + e3;
        int cc = wn*32 + nt*8 + qid*2;
        atomicAdd(&cred[cc],   e0 + e2);
        atomicAdd(&cred[cc+1], e1 + e3);
        if (inC) {
            int i0 = ti + wm*16 + gid;
            int jj = tj + cc;
            *(float2*)&d_C[((size_t)b*NREAL + i0)*NREAL + jj]     = make_float2(e0, e1);
            *(float2*)&d_C[((size_t)b*NREAL + i0 + 8)*NREAL + jj] = make_float2(e2, e3);
        }
    }
    atomicAdd(&rred[wm*16 + gid],     rs0);
    atomicAdd(&rred[wm*16 + 8 + gid], rs1);
    __syncthreads();
    if (tid < 64) {
        atomicAdd(&d_rsum[b*NPTS + ti + tid], rred[tid]);
        atomicAdd(&d_csum[b*NPTS + tj + tid], cred[tid]);
    }
}

// ---------------- hinge GEMM: sum relu(0.1 - x3 @ x4T) ----------------
__global__ __launch_bounds__(256) void hinge_mma_kernel() {
    __shared__ __nv_bfloat16 sAhi[64*40], sAlo[64*40], sBhi[64*40], sBlo[64*40];
    __shared__ float wsum[8];
    const int b = blockIdx.z;
    const int ti = blockIdx.y*64, tj = blockIdx.x*64;
    const size_t boff = (size_t)b*NPAD*DIM;

    float acc[4][4];
    #pragma unroll
    for (int nt = 0; nt < 4; nt++)
        #pragma unroll
        for (int k = 0; k < 4; k++) acc[nt][k] = 0.f;

    mma_mainloop(d_h3hi + boff, d_h3lo + boff, d_h4hi + boff, d_h4lo + boff,
                 ti, tj, sAhi, sAlo, sBhi, sBlo, acc);

    float h = 0.f;
    #pragma unroll
    for (int nt = 0; nt < 4; nt++)
        #pragma unroll
        for (int k = 0; k < 4; k++) h += fmaxf(0.1f - acc[nt][k], 0.f);

    #pragma unroll
    for (int o = 16; o; o >>= 1) h += __shfl_xor_sync(0xffffffffu, h, o);
    int warp = threadIdx.x >> 5, lane = threadIdx.x & 31;
    if (lane == 0) wsum[warp] = h;
    __syncthreads();
    if (threadIdx.x == 0) {
        float t = 0.f;
        #pragma unroll
        for (int k = 0; k < 8; k++) t += wsum[k];
        atomicAdd(&d_hinge, t);
    }
}

// ---------------- C = 1 - s/(c_j + r_i - s); write Ct ----------------
__global__ void cmat_kernel() {   // block (32,8), grid (16,16,16)
    __shared__ float tile[32][33];
    int b = blockIdx.z, i0 = blockIdx.y*32, j0 = blockIdx.x*32;
    #pragma unroll
    for (int u = 0; u < 4; u++) {
        int i = i0 + threadIdx.y + u*8;
        int j = j0 + threadIdx.x;
        size_t idx = ((size_t)b*NREAL + i)*NREAL + j;
        float s  = d_C[idx];
        float cv = 1.0f - s / (d_csum[b*NPTS + j] + d_rsum[b*NPTS + i] - s);
        d_C[idx] = cv;
        tile[threadIdx.y + u*8][threadIdx.x] = cv;
    }
    __syncthreads();
    #pragma unroll
    for (int u = 0; u < 4; u++) {
        int jj = j0 + threadIdx.y + u*8;
        int ii = i0 + threadIdx.x;
        d_Ct[((size_t)b*NREAL + jj)*NREAL + ii] = tile[threadIdx.x][threadIdx.y + u*8];
    }
}

// ---------------- softmin: one warp per (dir, b, i) row ----------------
__global__ __launch_bounds__(256) void softmin_kernel(int mode, float eps, int par) {
    int gw   = (blockIdx.x*256 + threadIdx.x) >> 5;
    int lane = threadIdx.x & 31;
    int dir  = gw >> 13;
    int rem  = gw & 8191;
    int b    = rem >> 9;
    int i    = rem & 511;

    const float* fin  = par ? d_fB : d_fA;
    const float* gin  = par ? d_gB : d_gA;
    float*       fout = par ? d_fA : d_fB;
    float*       gout = par ? d_gA : d_gB;

    const float* Crow = (dir ? d_Ct : d_C) + ((size_t)b*NREAL + i)*NREAL;
    const float* h    = (dir ? fin : gin) + b*NREAL;

    float t[16];
    float m = -3.0e38f;
    #pragma unroll
    for (int k = 0; k < 16; k++) {
        int j = (k << 5) + lane;
        float hv = (mode == 0) ? 0.0f : __ldg(&h[j]);
        t[k] = hv - __ldg(&Crow[j]);
        m = fmaxf(m, t[k]);
    }
    #pragma unroll
    for (int o = 16; o; o >>= 1) m = fmaxf(m, __shfl_xor_sync(0xffffffffu, m, o));

    float a = 1.44269504088896341f / eps;
    float s = 0.f;
    #pragma unroll
    for (int k = 0; k < 16; k++) s += exp2f((t[k] - m) * a);
    #pragma unroll
    for (int o = 16; o; o >>= 1) s += __shfl_xor_sync(0xffffffffu, s, o);

    if (lane == 0) {
        float out = -m - eps * 0.6931471805599453f * log2f(s);
        int idx = b*NREAL + i;
        if (dir == 0) fout[idx] = (mode == 1) ? 0.5f*(fin[idx] + out) : out;
        else          gout[idx] = (mode == 1) ? 0.5f*(gin[idx] + out) : out;
    }
}

// ---------------- final reduction ----------------
__global__ void reduce_kernel(float* __restrict__ out) {
    float s = 0.f;
    for (int idx = threadIdx.x; idx < BATCH*NREAL; idx += 256)
        s += d_fB[idx] + d_gB[idx];
    #pragma unroll
    for (int o = 16; o; o >>= 1) s += __shfl_xor_sync(0xffffffffu, s, o);
    __shared__ float w[8];
    int warp = threadIdx.x >> 5, lane = threadIdx.x & 31;
    if (lane == 0) w[warp] = s;
    __syncthreads();
    if (threadIdx.x == 0) {
        float t = 0.f;
        #pragma unroll
        for (int k = 0; k < 8; k++) t += w[k];
        out[0] = d_hinge;
        out[1] = t * (1.0f / BATCH);
    }
}

// ---------------- launch ----------------
extern "C" void kernel_launch(void* const* d_in, const int* in_sizes, int n_in,
                              void* d_out, int out_size) {
    const float* x1 = (const float*)d_in[0];
    const float* x2 = (const float*)d_in[1];
    const float* x3 = (const float*)d_in[2];
    const float* x4 = (const float*)d_in[3];
    float* out = (float*)d_out;

    static const float EPS[8] = {9.0f, 9.0f, 2.25f, 0.5625f, 0.140625f,
                                 0.03515625f, 0.0087890625f, 0.0025f};

    zero_kernel<<<56, 256>>>();
    prep_kernel<<<5120, 256>>>(x1, x2, x3, x4);
    sim_mma_kernel<<<dim3(14,14,16), 256>>>();
    cmat_kernel<<<dim3(16,16,16), dim3(32,8)>>>();

    softmin_kernel<<<2048, 256>>>(0, 9.0f, 1);
    for (int it = 0; it < 8; it++)
        softmin_kernel<<<2048, 256>>>(1, EPS[it], it & 1);
    softmin_kernel<<<2048, 256>>>(2, 0.0025f, 0);

    hinge_mma_kernel<<<dim3(6,6,16), 256>>>();
    reduce_kernel<<<1, 256>>>(out);
}

// round 11
// speedup vs baseline: 1.5282x; 1.1072x over previous
#include <cuda_runtime.h>
#include <cuda_bf16.h>

#define BATCH 16
#define NPTS  896
#define NREAL 512
#define DIM   256
#define NPAD  384

// ---------------- scratch ----------------
__device__ __nv_bfloat16 d_f1hi[BATCH*NPTS*DIM], d_f1lo[BATCH*NPTS*DIM];
__device__ __nv_bfloat16 d_f2hi[BATCH*NPTS*DIM], d_f2lo[BATCH*NPTS*DIM];
__device__ __nv_bfloat16 d_h3hi[BATCH*NPAD*DIM], d_h3lo[BATCH*NPAD*DIM];
__device__ __nv_bfloat16 d_h4hi[BATCH*NPAD*DIM], d_h4lo[BATCH*NPAD*DIM];
__device__ float d_C  [BATCH*NREAL*NREAL];
__device__ float d_Ct [BATCH*NREAL*NREAL];
__device__ float d_rsum[BATCH*NPTS];
__device__ float d_csum[BATCH*NPTS];
__device__ float d_fA[BATCH*NREAL], d_gA[BATCH*NREAL];
__device__ float d_fB[BATCH*NREAL], d_gB[BATCH*NREAL];
__device__ float d_hinge;
__device__ unsigned d_bar_cnt;
__device__ unsigned d_bar_gen;

// ---------------- primitives ----------------
__device__ __forceinline__ unsigned s2u(const void* p) {
    return (unsigned)__cvta_generic_to_shared(p);
}
__device__ __forceinline__ void ldm4(unsigned r[4], unsigned addr) {
    asm volatile("ldmatrix.sync.aligned.m8n8.x4.shared.b16 {%0,%1,%2,%3}, [%4];\n"
        : "=r"(r[0]), "=r"(r[1]), "=r"(r[2]), "=r"(r[3]) : "r"(addr));
}
__device__ __forceinline__ void mma16816(float acc[4], const unsigned a[4],
                                         unsigned b0, unsigned b1) {
    asm volatile("mma.sync.aligned.m16n8k16.row.col.f32.bf16.bf16.f32 "
        "{%0,%1,%2,%3},{%4,%5,%6,%7},{%8,%9},{%0,%1,%2,%3};\n"
        : "+f"(acc[0]), "+f"(acc[1]), "+f"(acc[2]), "+f"(acc[3])
        : "r"(a[0]), "r"(a[1]), "r"(a[2]), "r"(a[3]), "r"(b0), "r"(b1));
}
__device__ __forceinline__ void cpasync16(unsigned dst, const void* src) {
    asm volatile("cp.async.cg.shared.global [%0], [%1], 16;\n" :: "r"(dst), "l"(src));
}
__device__ __forceinline__ void cpcommit() {
    asm volatile("cp.async.commit_group;\n" ::: "memory");
}

// smem per stage: Ahi(10240) Alo Bhi Blo ; stage stride 40960 ; total 81920
#define MOFF   10240
#define STOFF  40960
#define SMEM_G 81920
#define KE 14.4269504088896341f

// ---------------- zero ----------------
__global__ void zero_kernel() {
    int i = blockIdx.x * blockDim.x + threadIdx.x;
    if (i < BATCH*NPTS) { d_rsum[i] = 0.f; d_csum[i] = 0.f; }
    if (i == 0) { d_hinge = 0.f; d_bar_cnt = 0u; d_bar_gen = 0u; }
}

// ---------------- prep: normalize + bf16 hi/lo split ----------------
__device__ __forceinline__ void split_store4(__nv_bfloat16* hi, __nv_bfloat16* lo,
                                             float4 v, float scale) {
    float a[4] = {v.x*scale, v.y*scale, v.z*scale, v.w*scale};
    __nv_bfloat16 h[4], l[4];
    #pragma unroll
    for (int i = 0; i < 4; i++) {
        h[i] = __float2bfloat16(a[i]);
        l[i] = __float2bfloat16(a[i] - __bfloat162float(h[i]));
    }
    *(uint2*)hi = *(uint2*)h;
    *(uint2*)lo = *(uint2*)l;
}

__global__ __launch_bounds__(256) void prep_kernel(
    const float* __restrict__ x1, const float* __restrict__ x2,
    const float* __restrict__ x3, const float* __restrict__ x4)
{
    int w    = (blockIdx.x * 256 + threadIdx.x) >> 5;
    int lane = threadIdx.x & 31;

    if (w < 2*BATCH*NPTS) {
        int tensor = w / (BATCH*NPTS);
        int r      = w - tensor * (BATCH*NPTS);
        int b = r / NPTS;
        int i = r - b * NPTS;
        const float* src;
        if (tensor == 0)
            src = (i < NREAL) ? x1 + ((size_t)b*NREAL + i)*DIM
                              : x3 + ((size_t)b*NPAD + (i-NREAL))*DIM;
        else
            src = (i < NREAL) ? x2 + ((size_t)b*NREAL + i)*DIM
                              : x4 + ((size_t)b*NPAD + (i-NREAL))*DIM;
        size_t off = ((size_t)b*NPTS + i)*DIM;
        __nv_bfloat16* hi = (tensor ? d_f2hi : d_f1hi) + off;
        __nv_bfloat16* lo = (tensor ? d_f2lo : d_f1lo) + off;

        float4 v0 = *(const float4*)(src + lane*4);
        float4 v1 = *(const float4*)(src + 128 + lane*4);
        float ss = v0.x*v0.x + v0.y*v0.y + v0.z*v0.z + v0.w*v0.w
                 + v1.x*v1.x + v1.y*v1.y + v1.z*v1.z + v1.w*v1.w;
        #pragma unroll
        for (int o = 16; o; o >>= 1) ss += __shfl_xor_sync(0xffffffffu, ss, o);
        float inv = 1.0f / fmaxf(sqrtf(ss), 1e-12f);
        split_store4(hi + lane*4,       lo + lane*4,       v0, inv);
        split_store4(hi + 128 + lane*4, lo + 128 + lane*4, v1, inv);
    } else {
        int w2 = w - 2*BATCH*NPTS;
        int tensor = w2 / (BATCH*NPAD);
        int r      = w2 - tensor * (BATCH*NPAD);
        int b = r / NPAD;
        int i = r - b * NPAD;
        const float* src = (tensor ? x4 : x3) + ((size_t)b*NPAD + i)*DIM;
        size_t off = ((size_t)b*NPAD + i)*DIM;
        __nv_bfloat16* hi = (tensor ? d_h4hi : d_h3hi) + off;
        __nv_bfloat16* lo = (tensor ? d_h4lo : d_h3lo) + off;
        float4 v0 = *(const float4*)(src + lane*4);
        float4 v1 = *(const float4*)(src + 128 + lane*4);
        split_store4(hi + lane*4,       lo + lane*4,       v0, 1.0f);
        split_store4(hi + 128 + lane*4, lo + 128 + lane*4, v1, 1.0f);
    }
}

// ---------------- 128x128 double-buffered HMMA mainloop ----------------
__device__ __forceinline__ void stage_load(unsigned sb,
    const __nv_bfloat16* __restrict__ Ahi, const __nv_bfloat16* __restrict__ Alo,
    const __nv_bfloat16* __restrict__ Bhi, const __nv_bfloat16* __restrict__ Blo,
    int kc, int tid)
{
    #pragma unroll
    for (int p = 0; p < 2; p++) {
        int id = tid + p*256;               // 0..511
        int row = id >> 2, c4 = id & 3;
        unsigned doff = (unsigned)(row*40 + c4*8)*2;
        size_t goff = (size_t)row*DIM + kc + c4*8;
        cpasync16(sb + 0*MOFF + doff, Ahi + goff);
        cpasync16(sb + 1*MOFF + doff, Alo + goff);
        cpasync16(sb + 2*MOFF + doff, Bhi + goff);
        cpasync16(sb + 3*MOFF + doff, Blo + goff);
    }
}

__device__ __forceinline__ void mma_stage(float acc[2][8][4], unsigned sb,
                                          int wm, int wn, int l)
{
    unsigned rowA = (unsigned)((wm*32 + (l & 15))*40 + (l >> 4)*8) * 2;
    unsigned rowB = (unsigned)((wn*64 + (l & 7) + ((l >> 4) & 1)*8)*40
                               + ((l >> 3) & 1)*8) * 2;
    #pragma unroll
    for (int ks = 0; ks < 2; ks++) {
        unsigned ko = ks*32;
        unsigned ahi[2][4], alo[2][4], bhi[4][4], blo[4][4];
        #pragma unroll
        for (int mt = 0; mt < 2; mt++) {
            ldm4(ahi[mt], sb + 0*MOFF + rowA + mt*1280u + ko);
            ldm4(alo[mt], sb + 1*MOFF + rowA + mt*1280u + ko);
        }
        #pragma unroll
        for (int bt = 0; bt < 4; bt++) {
            ldm4(bhi[bt], sb + 2*MOFF + rowB + bt*1280u + ko);
            ldm4(blo[bt], sb + 3*MOFF + rowB + bt*1280u + ko);
        }
        #pragma unroll
        for (int mt = 0; mt < 2; mt++)
            #pragma unroll
            for (int nt = 0; nt < 8; nt++) {
                int bt = nt >> 1, pr = (nt & 1)*2;
                mma16816(acc[mt][nt], ahi[mt], bhi[bt][pr], bhi[bt][pr+1]);
                mma16816(acc[mt][nt], ahi[mt], blo[bt][pr], blo[bt][pr+1]);
                mma16816(acc[mt][nt], alo[mt], bhi[bt][pr], bhi[bt][pr+1]);
            }
    }
}

__device__ __forceinline__ void mma_mainloop128(float acc[2][8][4], unsigned sb,
    const __nv_bfloat16* __restrict__ Ahi, const __nv_bfloat16* __restrict__ Alo,
    const __nv_bfloat16* __restrict__ Bhi, const __nv_bfloat16* __restrict__ Blo,
    int tid, int wm, int wn, int l)
{
    stage_load(sb, Ahi, Alo, Bhi, Blo, 0, tid);
    cpcommit();
    for (int c = 0; c < 8; c++) {
        int s = c & 1;
        if (c < 7) {
            stage_load(sb + (1-s)*STOFF, Ahi, Alo, Bhi, Blo, (c+1)*32, tid);
            cpcommit();
            asm volatile("cp.async.wait_group 1;\n" ::: "memory");
        } else {
            asm volatile("cp.async.wait_group 0;\n" ::: "memory");
        }
        __syncthreads();
        mma_stage(acc, sb + s*STOFF, wm, wn, l);
        __syncthreads();
    }
}

// ---------------- sim GEMM (128x128 tiles) + exp + row/col sums ----------------
__global__ __launch_bounds__(256) void sim_mma_kernel() {
    extern __shared__ char smem[];
    const unsigned sb = s2u(smem);
    const int tid = threadIdx.x;
    const int w = tid >> 5, l = tid & 31;
    const int wm = w & 3, wn = w >> 2;
    const int gid = l >> 2, qid = l & 3;
    const int b = blockIdx.z;
    const int ti = blockIdx.y*128, tj = blockIdx.x*128;
    const size_t boff = (size_t)b*NPTS*DIM;

    float acc[2][8][4];
    #pragma unroll
    for (int mt = 0; mt < 2; mt++)
        #pragma unroll
        for (int nt = 0; nt < 8; nt++)
            #pragma unroll
            for (int k = 0; k < 4; k++) acc[mt][nt][k] = 0.f;

    mma_mainloop128(acc, sb,
        d_f1hi + boff + (size_t)ti*DIM, d_f1lo + boff + (size_t)ti*DIM,
        d_f2hi + boff + (size_t)tj*DIM, d_f2lo + boff + (size_t)tj*DIM,
        tid, wm, wn, l);

    float* srs = (float*)smem;            // 128 floats
    float* scs = (float*)(smem + 512);    // 128 floats
    if (tid < 128) { srs[tid] = 0.f; scs[tid] = 0.f; }
    __syncthreads();

    float rp[4] = {0.f, 0.f, 0.f, 0.f};
    #pragma unroll
    for (int nt = 0; nt < 8; nt++) {
        float c0 = 0.f, c1 = 0.f;
        #pragma unroll
        for (int mt = 0; mt < 2; mt++) {
            float e0 = exp2f(acc[mt][nt][0]*KE);
            float e1 = exp2f(acc[mt][nt][1]*KE);
            float e2 = exp2f(acc[mt][nt][2]*KE);
            float e3 = exp2f(acc[mt][nt][3]*KE);
            acc[mt][nt][0] = e0; acc[mt][nt][1] = e1;
            acc[mt][nt][2] = e2; acc[mt][nt][3] = e3;
            rp[mt*2+0] += e0 + e1;
            rp[mt*2+1] += e2 + e3;
            c0 += e0 + e2;
            c1 += e1 + e3;
        }
        #pragma unroll
        for (int o = 4; o <= 16; o <<= 1) {
            c0 += __shfl_xor_sync(0xffffffffu, c0, o);
            c1 += __shfl_xor_sync(0xffffffffu, c1, o);
        }
        if (gid == 0) {
            atomicAdd(&scs[wn*64 + nt*8 + qid*2],     c0);
            atomicAdd(&scs[wn*64 + nt*8 + qid*2 + 1], c1);
        }
    }
    atomicAdd(&srs[wm*32 +      gid], rp[0]);
    atomicAdd(&srs[wm*32 +  8 + gid], rp[1]);
    atomicAdd(&srs[wm*32 + 16 + gid], rp[2]);
    atomicAdd(&srs[wm*32 + 24 + gid], rp[3]);

    if (blockIdx.x < 4 && blockIdx.y < 4) {
        #pragma unroll
        for (int mt = 0; mt < 2; mt++)
            #pragma unroll
            for (int nt = 0; nt < 8; nt++) {
                int row = ti + wm*32 + mt*16 + gid;
                int col = tj + wn*64 + nt*8 + qid*2;
                *(float2*)&d_C[((size_t)b*NREAL + row)*NREAL + col] =
                    make_float2(acc[mt][nt][0], acc[mt][nt][1]);
                *(float2*)&d_C[((size_t)b*NREAL + row + 8)*NREAL + col] =
                    make_float2(acc[mt][nt][2], acc[mt][nt][3]);
            }
    }
    __syncthreads();
    if (tid < 128) {
        atomicAdd(&d_rsum[b*NPTS + ti + tid], srs[tid]);
        atomicAdd(&d_csum[b*NPTS + tj + tid], scs[tid]);
    }
}

// ---------------- hinge GEMM (128x128 tiles) ----------------
__global__ __launch_bounds__(256) void hinge_mma_kernel() {
    extern __shared__ char smem[];
    const unsigned sb = s2u(smem);
    const int tid = threadIdx.x;
    const int w = tid >> 5, l = tid & 31;
    const int wm = w & 3, wn = w >> 2;
    const int b = blockIdx.z;
    const int ti = blockIdx.y*128, tj = blockIdx.x*128;
    const size_t boff = (size_t)b*NPAD*DIM;

    float acc[2][8][4];
    #pragma unroll
    for (int mt = 0; mt < 2; mt++)
        #pragma unroll
        for (int nt = 0; nt < 8; nt++)
            #pragma unroll
            for (int k = 0; k < 4; k++) acc[mt][nt][k] = 0.f;

    mma_mainloop128(acc, sb,
        d_h3hi + boff + (size_t)ti*DIM, d_h3lo + boff + (size_t)ti*DIM,
        d_h4hi + boff + (size_t)tj*DIM, d_h4lo + boff + (size_t)tj*DIM,
        tid, wm, wn, l);

    float h = 0.f;
    #pragma unroll
    for (int mt = 0; mt < 2; mt++)
        #pragma unroll
        for (int nt = 0; nt < 8; nt++)
            #pragma unroll
            for (int k = 0; k < 4; k++)
                h += fmaxf(0.1f - acc[mt][nt][k], 0.f);

    #pragma unroll
    for (int o = 16; o; o >>= 1) h += __shfl_xor_sync(0xffffffffu, h, o);
    float* wsum = (float*)smem;
    if (l == 0) wsum[w] = h;
    __syncthreads();
    if (tid == 0) {
        float t = 0.f;
        #pragma unroll
        for (int k = 0; k < 8; k++) t += wsum[k];
        atomicAdd(&d_hinge, t);
    }
}

// ---------------- C = 1 - s/(c_j + r_i - s); write Ct ----------------
__global__ void cmat_kernel() {   // block (32,8), grid (16,16,16)
    __shared__ float tile[32][33];
    int b = blockIdx.z, i0 = blockIdx.y*32, j0 = blockIdx.x*32;
    #pragma unroll
    for (int u = 0; u < 4; u++) {
        int i = i0 + threadIdx.y + u*8;
        int j = j0 + threadIdx.x;
        size_t idx = ((size_t)b*NREAL + i)*NREAL + j;
        float s  = d_C[idx];
        float cv = 1.0f - s / (d_csum[b*NPTS + j] + d_rsum[b*NPTS + i] - s);
        d_C[idx] = cv;
        tile[threadIdx.y + u*8][threadIdx.x] = cv;
    }
    __syncthreads();
    #pragma unroll
    for (int u = 0; u < 4; u++) {
        int jj = j0 + threadIdx.y + u*8;
        int ii = i0 + threadIdx.x;
        d_Ct[((size_t)b*NREAL + jj)*NREAL + ii] = tile[threadIdx.x][threadIdx.y + u*8];
    }
}

// ---------------- fused softmin: 10 phases in one persistent kernel ----------------
// Cross-phase f/g reads MUST bypass L1 (__ldcg): phases write from other SMs and
// sm_103a L1 is only invalidated at launch boundaries, not by __threadfence.
#define SOFT_BLOCKS 296

__device__ __forceinline__ void grid_bar() {
    __syncthreads();
    if (threadIdx.x == 0) {
        __threadfence();
        volatile unsigned* genp = &d_bar_gen;
        unsigned g = *genp;
        if (atomicAdd(&d_bar_cnt, 1u) == (unsigned)(gridDim.x - 1)) {
            d_bar_cnt = 0u;
            __threadfence();
            atomicExch(&d_bar_gen, g + 1u);
        } else {
            while (*genp == g) { }
            __threadfence();
        }
    }
    __syncthreads();
}

__global__ __launch_bounds__(256, 2) void softmin_fused(float* __restrict__ out) {
    const int w = threadIdx.x >> 5, lane = threadIdx.x & 31;
    const int gwarp = blockIdx.x*8 + w;          // 0 .. 2367
    const int nwarps = SOFT_BLOCKS*8;

    const float epsv[10] = {9.f, 9.f, 9.f, 2.25f, 0.5625f, 0.140625f,
                            0.03515625f, 0.0087890625f, 0.0025f, 0.0025f};
    const int   modev[10] = {0,1,1,1,1,1,1,1,1,2};
    const int   parv[10]  = {1,0,1,0,1,0,1,0,1,0};

    for (int p = 0; p < 10; p++) {
        const float eps = epsv[p];
        const int mode = modev[p], par = parv[p];
        const float* fin  = par ? d_fB : d_fA;
        const float* gin  = par ? d_gB : d_gA;
        float*       fout = par ? d_fA : d_fB;
        float*       gout = par ? d_gA : d_gB;
        const float a = 1.44269504088896341f / eps;

        for (int gw = gwarp; gw < 16384; gw += nwarps) {
            int dir = gw >> 13;
            int rem = gw & 8191;
            int b   = rem >> 9;
            int i   = rem & 511;

            const float* Crow = (dir ? d_Ct : d_C) + ((size_t)b*NREAL + i)*NREAL;
            const float* h    = (dir ? fin : gin) + b*NREAL;

            float t[16];
            float m = -3.0e38f;
            #pragma unroll
            for (int k = 0; k < 16; k++) {
                int j = (k << 5) + lane;
                float hv = (mode == 0) ? 0.0f : __ldcg(&h[j]);
                t[k] = hv - __ldg(&Crow[j]);
                m = fmaxf(m, t[k]);
            }
            #pragma unroll
            for (int o = 16; o; o >>= 1) m = fmaxf(m, __shfl_xor_sync(0xffffffffu, m, o));

            float s = 0.f;
            #pragma unroll
            for (int k = 0; k < 16; k++) s += exp2f((t[k] - m) * a);
            #pragma unroll
            for (int o = 16; o; o >>= 1) s += __shfl_xor_sync(0xffffffffu, s, o);

            if (lane == 0) {
                float o2 = -m - eps * 0.6931471805599453f * log2f(s);
                int idx = b*NREAL + i;
                if (dir == 0)
                    fout[idx] = (mode == 1) ? 0.5f*(__ldcg(&fin[idx]) + o2) : o2;
                else
                    gout[idx] = (mode == 1) ? 0.5f*(__ldcg(&gin[idx]) + o2) : o2;
            }
        }
        grid_bar();
    }

    // final reduction by block 0 (all writes visible after last grid_bar)
    if (blockIdx.x == 0) {
        float s = 0.f;
        for (int idx = threadIdx.x; idx < BATCH*NREAL; idx += 256)
            s += __ldcg(&d_fB[idx]) + __ldcg(&d_gB[idx]);
        #pragma unroll
        for (int o = 16; o; o >>= 1) s += __shfl_xor_sync(0xffffffffu, s, o);
        __shared__ float ws[8];
        if (lane == 0) ws[w] = s;
        __syncthreads();
        if (threadIdx.x == 0) {
            float t = 0.f;
            #pragma unroll
            for (int k = 0; k < 8; k++) t += ws[k];
            out[0] = d_hinge;
            out[1] = t * (1.0f / BATCH);
        }
    }
}

// ---------------- launch ----------------
extern "C" void kernel_launch(void* const* d_in, const int* in_sizes, int n_in,
                              void* d_out, int out_size) {
    const float* x1 = (const float*)d_in[0];
    const float* x2 = (const float*)d_in[1];
    const float* x3 = (const float*)d_in[2];
    const float* x4 = (const float*)d_in[3];
    float* out = (float*)d_out;

    cudaFuncSetAttribute(sim_mma_kernel,
        cudaFuncAttributeMaxDynamicSharedMemorySize, SMEM_G);
    cudaFuncSetAttribute(hinge_mma_kernel,
        cudaFuncAttributeMaxDynamicSharedMemorySize, SMEM_G);

    zero_kernel<<<56, 256>>>();
    prep_kernel<<<5120, 256>>>(x1, x2, x3, x4);
    sim_mma_kernel<<<dim3(7,7,16), 256, SMEM_G>>>();
    cmat_kernel<<<dim3(16,16,16), dim3(32,8)>>>();
    hinge_mma_kernel<<<dim3(3,3,16), 256, SMEM_G>>>();
    softmin_fused<<<SOFT_BLOCKS, 256>>>(out);
}

// round 16
// speedup vs baseline: 1.5958x; 1.0443x over previous
#include <cuda_runtime.h>
#include <cuda_bf16.h>

#define BATCH 16
#define NPTS  896
#define NREAL 512
#define DIM   256
#define NPAD  384

// ---------------- scratch ----------------
__device__ __nv_bfloat16 d_f1hi[BATCH*NPTS*DIM], d_f1lo[BATCH*NPTS*DIM];
__device__ __nv_bfloat16 d_f2hi[BATCH*NPTS*DIM], d_f2lo[BATCH*NPTS*DIM];
__device__ __nv_bfloat16 d_h3hi[BATCH*NPAD*DIM], d_h3lo[BATCH*NPAD*DIM];
__device__ __nv_bfloat16 d_h4hi[BATCH*NPAD*DIM], d_h4lo[BATCH*NPAD*DIM];
__device__ float d_C  [BATCH*NREAL*NREAL];
__device__ float d_Ct [BATCH*NREAL*NREAL];
__device__ float d_rsum[BATCH*NPTS];
__device__ float d_csum[BATCH*NPTS];
__device__ float d_fA[BATCH*NREAL], d_gA[BATCH*NREAL];
__device__ float d_fB[BATCH*NREAL], d_gB[BATCH*NREAL];
__device__ float d_hinge;
__device__ unsigned d_bar_cnt;
__device__ unsigned d_bar_gen;

// ---------------- primitives ----------------
__device__ __forceinline__ unsigned s2u(const void* p) {
    return (unsigned)__cvta_generic_to_shared(p);
}
__device__ __forceinline__ void ldm4(unsigned r[4], unsigned addr) {
    asm volatile("ldmatrix.sync.aligned.m8n8.x4.shared.b16 {%0,%1,%2,%3}, [%4];\n"
        : "=r"(r[0]), "=r"(r[1]), "=r"(r[2]), "=r"(r[3]) : "r"(addr));
}
__device__ __forceinline__ void mma16816(float acc[4], const unsigned a[4],
                                         unsigned b0, unsigned b1) {
    asm volatile("mma.sync.aligned.m16n8k16.row.col.f32.bf16.bf16.f32 "
        "{%0,%1,%2,%3},{%4,%5,%6,%7},{%8,%9},{%0,%1,%2,%3};\n"
        : "+f"(acc[0]), "+f"(acc[1]), "+f"(acc[2]), "+f"(acc[3])
        : "r"(a[0]), "r"(a[1]), "r"(a[2]), "r"(a[3]), "r"(b0), "r"(b1));
}
__device__ __forceinline__ void cpasync16(unsigned dst, const void* src) {
    asm volatile("cp.async.cg.shared.global [%0], [%1], 16;\n" :: "r"(dst), "l"(src));
}
__device__ __forceinline__ void cpcommit() {
    asm volatile("cp.async.commit_group;\n" ::: "memory");
}

// smem per stage: Ahi(10240) Alo Bhi Blo ; stage stride 40960 ; total 81920
#define MOFF   10240
#define STOFF  40960
#define SMEM_G 81920
#define KE 14.4269504088896341f

// ---------------- prep: normalize + bf16 hi/lo split (+ zero accumulators) ----
__device__ __forceinline__ void split_store4(__nv_bfloat16* hi, __nv_bfloat16* lo,
                                             float4 v, float scale) {
    float a[4] = {v.x*scale, v.y*scale, v.z*scale, v.w*scale};
    __nv_bfloat16 h[4], l[4];
    #pragma unroll
    for (int i = 0; i < 4; i++) {
        h[i] = __float2bfloat16(a[i]);
        l[i] = __float2bfloat16(a[i] - __bfloat162float(h[i]));
    }
    *(uint2*)hi = *(uint2*)h;
    *(uint2*)lo = *(uint2*)l;
}

__global__ __launch_bounds__(256) void prep_kernel(
    const float* __restrict__ x1, const float* __restrict__ x2,
    const float* __restrict__ x3, const float* __restrict__ x4)
{
    // merged zero: first 56 blocks clear accumulators (consumed by later kernels)
    if (blockIdx.x < 56) {
        int z = blockIdx.x * 256 + threadIdx.x;
        if (z < BATCH*NPTS) { d_rsum[z] = 0.f; d_csum[z] = 0.f; }
        if (z == 0) { d_hinge = 0.f; d_bar_cnt = 0u; d_bar_gen = 0u; }
    }

    int w    = (blockIdx.x * 256 + threadIdx.x) >> 5;
    int lane = threadIdx.x & 31;

    if (w < 2*BATCH*NPTS) {
        int tensor = w / (BATCH*NPTS);
        int r      = w - tensor * (BATCH*NPTS);
        int b = r / NPTS;
        int i = r - b * NPTS;
        const float* src;
        if (tensor == 0)
            src = (i < NREAL) ? x1 + ((size_t)b*NREAL + i)*DIM
                              : x3 + ((size_t)b*NPAD + (i-NREAL))*DIM;
        else
            src = (i < NREAL) ? x2 + ((size_t)b*NREAL + i)*DIM
                              : x4 + ((size_t)b*NPAD + (i-NREAL))*DIM;
        size_t off = ((size_t)b*NPTS + i)*DIM;
        __nv_bfloat16* hi = (tensor ? d_f2hi : d_f1hi) + off;
        __nv_bfloat16* lo = (tensor ? d_f2lo : d_f1lo) + off;

        float4 v0 = *(const float4*)(src + lane*4);
        float4 v1 = *(const float4*)(src + 128 + lane*4);
        float ss = v0.x*v0.x + v0.y*v0.y + v0.z*v0.z + v0.w*v0.w
                 + v1.x*v1.x + v1.y*v1.y + v1.z*v1.z + v1.w*v1.w;
        #pragma unroll
        for (int o = 16; o; o >>= 1) ss += __shfl_xor_sync(0xffffffffu, ss, o);
        float inv = 1.0f / fmaxf(sqrtf(ss), 1e-12f);
        split_store4(hi + lane*4,       lo + lane*4,       v0, inv);
        split_store4(hi + 128 + lane*4, lo + 128 + lane*4, v1, inv);
    } else {
        int w2 = w - 2*BATCH*NPTS;
        int tensor = w2 / (BATCH*NPAD);
        int r      = w2 - tensor * (BATCH*NPAD);
        int b = r / NPAD;
        int i = r - b * NPAD;
        const float* src = (tensor ? x4 : x3) + ((size_t)b*NPAD + i)*DIM;
        size_t off = ((size_t)b*NPAD + i)*DIM;
        __nv_bfloat16* hi = (tensor ? d_h4hi : d_h3hi) + off;
        __nv_bfloat16* lo = (tensor ? d_h4lo : d_h3lo) + off;
        float4 v0 = *(const float4*)(src + lane*4);
        float4 v1 = *(const float4*)(src + 128 + lane*4);
        split_store4(hi + lane*4,       lo + lane*4,       v0, 1.0f);
        split_store4(hi + 128 + lane*4, lo + 128 + lane*4, v1, 1.0f);
    }
}

// ---------------- 128x128 double-buffered HMMA mainloop ----------------
__device__ __forceinline__ void stage_load(unsigned sb,
    const __nv_bfloat16* __restrict__ Ahi, const __nv_bfloat16* __restrict__ Alo,
    const __nv_bfloat16* __restrict__ Bhi, const __nv_bfloat16* __restrict__ Blo,
    int kc, int tid)
{
    #pragma unroll
    for (int p = 0; p < 2; p++) {
        int id = tid + p*256;               // 0..511
        int row = id >> 2, c4 = id & 3;
        unsigned doff = (unsigned)(row*40 + c4*8)*2;
        size_t goff = (size_t)row*DIM + kc + c4*8;
        cpasync16(sb + 0*MOFF + doff, Ahi + goff);
        cpasync16(sb + 1*MOFF + doff, Alo + goff);
        cpasync16(sb + 2*MOFF + doff, Bhi + goff);
        cpasync16(sb + 3*MOFF + doff, Blo + goff);
    }
}

__device__ __forceinline__ void mma_stage(float acc[2][8][4], unsigned sb,
                                          int wm, int wn, int l)
{
    unsigned rowA = (unsigned)((wm*32 + (l & 15))*40 + (l >> 4)*8) * 2;
    unsigned rowB = (unsigned)((wn*64 + (l & 7) + ((l >> 4) & 1)*8)*40
                               + ((l >> 3) & 1)*8) * 2;
    #pragma unroll
    for (int ks = 0; ks < 2; ks++) {
        unsigned ko = ks*32;
        unsigned ahi[2][4], alo[2][4], bhi[4][4], blo[4][4];
        #pragma unroll
        for (int mt = 0; mt < 2; mt++) {
            ldm4(ahi[mt], sb + 0*MOFF + rowA + mt*1280u + ko);
            ldm4(alo[mt], sb + 1*MOFF + rowA + mt*1280u + ko);
        }
        #pragma unroll
        for (int bt = 0; bt < 4; bt++) {
            ldm4(bhi[bt], sb + 2*MOFF + rowB + bt*1280u + ko);
            ldm4(blo[bt], sb + 3*MOFF + rowB + bt*1280u + ko);
        }
        #pragma unroll
        for (int mt = 0; mt < 2; mt++)
            #pragma unroll
            for (int nt = 0; nt < 8; nt++) {
                int bt = nt >> 1, pr = (nt & 1)*2;
                mma16816(acc[mt][nt], ahi[mt], bhi[bt][pr], bhi[bt][pr+1]);
                mma16816(acc[mt][nt], ahi[mt], blo[bt][pr], blo[bt][pr+1]);
                mma16816(acc[mt][nt], alo[mt], bhi[bt][pr], bhi[bt][pr+1]);
            }
    }
}

__device__ __forceinline__ void mma_mainloop128(float acc[2][8][4], unsigned sb,
    const __nv_bfloat16* __restrict__ Ahi, const __nv_bfloat16* __restrict__ Alo,
    const __nv_bfloat16* __restrict__ Bhi, const __nv_bfloat16* __restrict__ Blo,
    int tid, int wm, int wn, int l)
{
    stage_load(sb, Ahi, Alo, Bhi, Blo, 0, tid);
    cpcommit();
    for (int c = 0; c < 8; c++) {
        int s = c & 1;
        if (c < 7) {
            stage_load(sb + (1-s)*STOFF, Ahi, Alo, Bhi, Blo, (c+1)*32, tid);
            cpcommit();
            asm volatile("cp.async.wait_group 1;\n" ::: "memory");
        } else {
            asm volatile("cp.async.wait_group 0;\n" ::: "memory");
        }
        __syncthreads();
        mma_stage(acc, sb + s*STOFF, wm, wn, l);
        __syncthreads();
    }
}

// ---------------- combined GEMM: 784 sim tiles + 144 hinge tiles ----------------
__global__ __launch_bounds__(256) void gemm_kernel() {
    extern __shared__ char smem[];
    const unsigned sb = s2u(smem);
    const int tid = threadIdx.x;
    const int w = tid >> 5, l = tid & 31;
    const int wm = w & 3, wn = w >> 2;
    const int gid = l >> 2, qid = l & 3;
    const int blk = blockIdx.x;
    const int is_sim = (blk < 784);

    int b, ti, tj;
    const __nv_bfloat16 *Ahi, *Alo, *Bhi, *Blo;
    if (is_sim) {
        b = blk / 49; int rem = blk - b*49;
        ti = (rem / 7) * 128; tj = (rem % 7) * 128;
        size_t boff = (size_t)b*NPTS*DIM;
        Ahi = d_f1hi + boff + (size_t)ti*DIM; Alo = d_f1lo + boff + (size_t)ti*DIM;
        Bhi = d_f2hi + boff + (size_t)tj*DIM; Blo = d_f2lo + boff + (size_t)tj*DIM;
    } else {
        int blk2 = blk - 784;
        b = blk2 / 9; int rem = blk2 - b*9;
        ti = (rem / 3) * 128; tj = (rem % 3) * 128;
        size_t boff = (size_t)b*NPAD*DIM;
        Ahi = d_h3hi + boff + (size_t)ti*DIM; Alo = d_h3lo + boff + (size_t)ti*DIM;
        Bhi = d_h4hi + boff + (size_t)tj*DIM; Blo = d_h4lo + boff + (size_t)tj*DIM;
    }

    float acc[2][8][4];
    #pragma unroll
    for (int mt = 0; mt < 2; mt++)
        #pragma unroll
        for (int nt = 0; nt < 8; nt++)
            #pragma unroll
            for (int k = 0; k < 4; k++) acc[mt][nt][k] = 0.f;

    mma_mainloop128(acc, sb, Ahi, Alo, Bhi, Blo, tid, wm, wn, l);

    if (is_sim) {
        float* srs = (float*)smem;            // 128 floats
        float* scs = (float*)(smem + 512);    // 128 floats
        if (tid < 128) { srs[tid] = 0.f; scs[tid] = 0.f; }
        __syncthreads();

        float rp[4] = {0.f, 0.f, 0.f, 0.f};
        #pragma unroll
        for (int nt = 0; nt < 8; nt++) {
            float c0 = 0.f, c1 = 0.f;
            #pragma unroll
            for (int mt = 0; mt < 2; mt++) {
                float e0 = exp2f(acc[mt][nt][0]*KE);
                float e1 = exp2f(acc[mt][nt][1]*KE);
                float e2 = exp2f(acc[mt][nt][2]*KE);
                float e3 = exp2f(acc[mt][nt][3]*KE);
                acc[mt][nt][0] = e0; acc[mt][nt][1] = e1;
                acc[mt][nt][2] = e2; acc[mt][nt][3] = e3;
                rp[mt*2+0] += e0 + e1;
                rp[mt*2+1] += e2 + e3;
                c0 += e0 + e2;
                c1 += e1 + e3;
            }
            #pragma unroll
            for (int o = 4; o <= 16; o <<= 1) {
                c0 += __shfl_xor_sync(0xffffffffu, c0, o);
                c1 += __shfl_xor_sync(0xffffffffu, c1, o);
            }
            if (gid == 0) {
                atomicAdd(&scs[wn*64 + nt*8 + qid*2],     c0);
                atomicAdd(&scs[wn*64 + nt*8 + qid*2 + 1], c1);
            }
        }
        atomicAdd(&srs[wm*32 +      gid], rp[0]);
        atomicAdd(&srs[wm*32 +  8 + gid], rp[1]);
        atomicAdd(&srs[wm*32 + 16 + gid], rp[2]);
        atomicAdd(&srs[wm*32 + 24 + gid], rp[3]);

        if (ti < NREAL && tj < NREAL) {
            #pragma unroll
            for (int mt = 0; mt < 2; mt++)
                #pragma unroll
                for (int nt = 0; nt < 8; nt++) {
                    int row = ti + wm*32 + mt*16 + gid;
                    int col = tj + wn*64 + nt*8 + qid*2;
                    *(float2*)&d_C[((size_t)b*NREAL + row)*NREAL + col] =
                        make_float2(acc[mt][nt][0], acc[mt][nt][1]);
                    *(float2*)&d_C[((size_t)b*NREAL + row + 8)*NREAL + col] =
                        make_float2(acc[mt][nt][2], acc[mt][nt][3]);
                }
        }
        __syncthreads();
        if (tid < 128) {
            atomicAdd(&d_rsum[b*NPTS + ti + tid], srs[tid]);
            atomicAdd(&d_csum[b*NPTS + tj + tid], scs[tid]);
        }
    } else {
        float h = 0.f;
        #pragma unroll
        for (int mt = 0; mt < 2; mt++)
            #pragma unroll
            for (int nt = 0; nt < 8; nt++)
                #pragma unroll
                for (int k = 0; k < 4; k++)
                    h += fmaxf(0.1f - acc[mt][nt][k], 0.f);

        #pragma unroll
        for (int o = 16; o; o >>= 1) h += __shfl_xor_sync(0xffffffffu, h, o);
        float* wsum = (float*)smem;
        if (l == 0) wsum[w] = h;
        __syncthreads();
        if (tid == 0) {
            float t = 0.f;
            #pragma unroll
            for (int k = 0; k < 8; k++) t += wsum[k];
            atomicAdd(&d_hinge, t);
        }
    }
}

// ---------------- C = 1 - s/(c_j + r_i - s); write Ct ----------------
__global__ void cmat_kernel() {   // block (32,8), grid (16,16,16)
    __shared__ float tile[32][33];
    int b = blockIdx.z, i0 = blockIdx.y*32, j0 = blockIdx.x*32;
    #pragma unroll
    for (int u = 0; u < 4; u++) {
        int i = i0 + threadIdx.y + u*8;
        int j = j0 + threadIdx.x;
        size_t idx = ((size_t)b*NREAL + i)*NREAL + j;
        float s  = d_C[idx];
        float cv = 1.0f - s / (d_csum[b*NPTS + j] + d_rsum[b*NPTS + i] - s);
        d_C[idx] = cv;
        tile[threadIdx.y + u*8][threadIdx.x] = cv;
    }
    __syncthreads();
    #pragma unroll
    for (int u = 0; u < 4; u++) {
        int jj = j0 + threadIdx.y + u*8;
        int ii = i0 + threadIdx.x;
        d_Ct[((size_t)b*NREAL + jj)*NREAL + ii] = tile[threadIdx.x][threadIdx.y + u*8];
    }
}

// ---------------- fused softmin: 10 phases in one persistent kernel ----------------
// Cross-phase f/g reads MUST bypass L1 (__ldcg): phases write from other SMs and
// sm_103a L1 is only invalidated at launch boundaries, not by __threadfence.
#define SOFT_BLOCKS 296

__device__ __forceinline__ void grid_bar() {
    __syncthreads();
    if (threadIdx.x == 0) {
        __threadfence();
        volatile unsigned* genp = &d_bar_gen;
        unsigned g = *genp;
        if (atomicAdd(&d_bar_cnt, 1u) == (unsigned)(gridDim.x - 1)) {
            d_bar_cnt = 0u;
            __threadfence();
            atomicExch(&d_bar_gen, g + 1u);
        } else {
            while (*genp == g) { }
            __threadfence();
        }
    }
    __syncthreads();
}

__global__ __launch_bounds__(256, 2) void softmin_fused(float* __restrict__ out) {
    const int w = threadIdx.x >> 5, lane = threadIdx.x & 31;
    const int gwarp = blockIdx.x*8 + w;          // 0 .. 2367
    const int nwarps = SOFT_BLOCKS*8;

    const float epsv[10] = {9.f, 9.f, 9.f, 2.25f, 0.5625f, 0.140625f,
                            0.03515625f, 0.0087890625f, 0.0025f, 0.0025f};
    const int   modev[10] = {0,1,1,1,1,1,1,1,1,2};
    const int   parv[10]  = {1,0,1,0,1,0,1,0,1,0};

    for (int p = 0; p < 10; p++) {
        const float eps = epsv[p];
        const int mode = modev[p], par = parv[p];
        const float* fin  = par ? d_fB : d_fA;
        const float* gin  = par ? d_gB : d_gA;
        float*       fout = par ? d_fA : d_fB;
        float*       gout = par ? d_gA : d_gB;
        const float a = 1.44269504088896341f / eps;

        for (int gw = gwarp; gw < 16384; gw += nwarps) {
            int dir = gw >> 13;
            int rem = gw & 8191;
            int b   = rem >> 9;
            int i   = rem & 511;

            const float4* Crow = (const float4*)
                ((dir ? d_Ct : d_C) + ((size_t)b*NREAL + i)*NREAL);
            const float4* h4 = (const float4*)(((dir ? fin : gin)) + b*NREAL);

            float4 t4[4];
            float m = -3.0e38f;
            #pragma unroll
            for (int k = 0; k < 4; k++) {
                float4 cv = __ldg(Crow + k*32 + lane);
                float4 hv = make_float4(0.f, 0.f, 0.f, 0.f);
                if (mode != 0) hv = __ldcg(h4 + k*32 + lane);
                t4[k].x = hv.x - cv.x;
                t4[k].y = hv.y - cv.y;
                t4[k].z = hv.z - cv.z;
                t4[k].w = hv.w - cv.w;
                m = fmaxf(m, fmaxf(fmaxf(t4[k].x, t4[k].y), fmaxf(t4[k].z, t4[k].w)));
            }
            #pragma unroll
            for (int o = 16; o; o >>= 1) m = fmaxf(m, __shfl_xor_sync(0xffffffffu, m, o));

            float s = 0.f;
            #pragma unroll
            for (int k = 0; k < 4; k++) {
                s += exp2f((t4[k].x - m) * a);
                s += exp2f((t4[k].y - m) * a);
                s += exp2f((t4[k].z - m) * a);
                s += exp2f((t4[k].w - m) * a);
            }
            #pragma unroll
            for (int o = 16; o; o >>= 1) s += __shfl_xor_sync(0xffffffffu, s, o);

            if (lane == 0) {
                float o2 = -m - eps * 0.6931471805599453f * log2f(s);
                int idx = b*NREAL + i;
                if (dir == 0)
                    fout[idx] = (mode == 1) ? 0.5f*(__ldcg(&fin[idx]) + o2) : o2;
                else
                    gout[idx] = (mode == 1) ? 0.5f*(__ldcg(&gin[idx]) + o2) : o2;
            }
        }
        grid_bar();
    }

    // final reduction by block 0 (all writes visible after last grid_bar)
    if (blockIdx.x == 0) {
        float s = 0.f;
        for (int idx = threadIdx.x; idx < BATCH*NREAL; idx += 256)
            s += __ldcg(&d_fB[idx]) + __ldcg(&d_gB[idx]);
        #pragma unroll
        for (int o = 16; o; o >>= 1) s += __shfl_xor_sync(0xffffffffu, s, o);
        __shared__ float ws[8];
        if (lane == 0) ws[w] = s;
        __syncthreads();
        if (threadIdx.x == 0) {
            float t = 0.f;
            #pragma unroll
            for (int k = 0; k < 8; k++) t += ws[k];
            out[0] = d_hinge;
            out[1] = t * (1.0f / BATCH);
        }
    }
}

// ---------------- launch ----------------
extern "C" void kernel_launch(void* const* d_in, const int* in_sizes, int n_in,
                              void* d_out, int out_size) {
    const float* x1 = (const float*)d_in[0];
    const float* x2 = (const float*)d_in[1];
    const float* x3 = (const float*)d_in[2];
    const float* x4 = (const float*)d_in[3];
    float* out = (float*)d_out;

    cudaFuncSetAttribute(gemm_kernel,
        cudaFuncAttributeMaxDynamicSharedMemorySize, SMEM_G);

    prep_kernel<<<5120, 256>>>(x1, x2, x3, x4);
    gemm_kernel<<<928, 256, SMEM_G>>>();
    cmat_kernel<<<dim3(16,16,16), dim3(32,8)>>>();
    softmin_fused<<<SOFT_BLOCKS, 256>>>(out);
}